// round 16
// baseline (speedup 1.0000x reference)
#include <cuda_runtime.h>
#include <cuda_bf16.h>
#include <math.h>
#include <stdint.h>

typedef __nv_bfloat16 bf16;

// ---------------------------------------------------------------------------
// Problem constants
// ---------------------------------------------------------------------------
static constexpr int B_   = 128;
static constexpr int C_   = 2048;
static constexpr int HW   = 49;
static constexpr int FIN  = 512;
static constexpr int G_   = 8;
static constexpr int NP   = 192;
static constexpr int S2   = 49;
static constexpr int SO3  = 455;
static constexpr int NG   = 4000;
static constexpr int GI   = 392;                // G_*S2
static constexpr size_t BC = (size_t)B_ * C_;   // 262144

static constexpr float RS192 = 0.07216878364870323f;
static constexpr float RS512 = 0.04419417382415922f;

// ---------------------------------------------------------------------------
// Scratch (device globals; runtime allocation is forbidden)
// ---------------------------------------------------------------------------
__device__ float d_P[HW * S2];
__device__ float d_q[S2];
__device__ float d_psi[FIN * GI];
__device__ float d_bpsi[GI];
__device__ float d_psi2[G_ * SO3];

// hi/lo bf16 planes (pre-split operands for the pipelined GEMMs)
__device__ __align__(16) bf16 d_ADh[(size_t)49 * BC];   // [i][b*2048+c]
__device__ __align__(16) bf16 d_ADl[(size_t)49 * BC];
// W2t planes: pad rows (j >= 8d) are NEVER written -> stay zero-initialized.
__device__ __align__(16) bf16 d_W2th[7 * 128 * C_];     // [l][j pad128][c]
__device__ __align__(16) bf16 d_W2tl[7 * 128 * C_];
// conv_w^T planes (RS512 folded) and psi^T planes for the pipelined W2 GEMM
__device__ __align__(16) bf16 d_cwTh[C_ * 512];         // [c][f]
__device__ __align__(16) bf16 d_cwTl[C_ * 512];
__device__ __align__(16) bf16 d_btWh[512 * 512];        // [gi pad512][f] (pad rows zero)
__device__ __align__(16) bf16 d_btWl[512 * 512];
__device__ __align__(16) bf16 d_x4h[1024 * 512];        // [b*8+g][so3 pad512]
__device__ __align__(16) bf16 d_x4l[1024 * 512];
__device__ __align__(16) bf16 d_bt5h[(size_t)4096 * 480]; // act_to^T planes
__device__ __align__(16) bf16 d_bt5l[(size_t)4096 * 480];
__device__ __align__(16) bf16 d_gacth[(size_t)1024 * 4096];
__device__ __align__(16) bf16 d_gactl[(size_t)1024 * 4096];
__device__ __align__(16) bf16 d_bt6h[(size_t)512 * 4096]; // act_from^T planes
__device__ __align__(16) bf16 d_bt6l[(size_t)512 * 4096];

__device__ float d_partD[(size_t)6 * 49 * 128 * 104];
__device__ float d_part6[(size_t)8 * 1024 * 512];
__device__ float d_x5[1024 * SO3];

__constant__ int c_off2[8] = {0, 1, 10, 35, 84, 165, 286, 455};
__constant__ int c_l_of_i[49] = {
    0, 1,1,1, 2,2,2,2,2, 3,3,3,3,3,3,3, 4,4,4,4,4,4,4,4,4,
    5,5,5,5,5,5,5,5,5,5,5, 6,6,6,6,6,6,6,6,6,6,6,6,6};

// ---------------------------------------------------------------------------
// helpers
// ---------------------------------------------------------------------------
__device__ __forceinline__ uint32_t smem_u32(const void* p) {
    uint32_t a;
    asm("{ .reg .u64 t; cvta.to.shared.u64 t, %1; cvt.u32.u64 %0, t; }"
        : "=r"(a) : "l"(p));
    return a;
}

__device__ __forceinline__ void ldsm4(uint32_t addr, uint32_t r[4]) {
    asm volatile("ldmatrix.sync.aligned.m8n8.x4.shared.b16 {%0,%1,%2,%3}, [%4];"
                 : "=r"(r[0]), "=r"(r[1]), "=r"(r[2]), "=r"(r[3]) : "r"(addr));
}

__device__ __forceinline__ void mma16816(float c[4], const uint32_t a[4],
                                         const uint32_t b[2]) {
    asm volatile(
        "mma.sync.aligned.m16n8k16.row.col.f32.bf16.bf16.f32 "
        "{%0,%1,%2,%3}, {%4,%5,%6,%7}, {%8,%9}, {%0,%1,%2,%3};"
        : "+f"(c[0]), "+f"(c[1]), "+f"(c[2]), "+f"(c[3])
        : "r"(a[0]), "r"(a[1]), "r"(a[2]), "r"(a[3]), "r"(b[0]), "r"(b[1]));
}

__device__ __forceinline__ void split2(float v, bf16& h, bf16& l) {
    h = __float2bfloat16(v);
    l = __float2bfloat16(v - __bfloat162float(h));
}

__device__ __forceinline__ uint32_t pack2(bf16 a, bf16 b) {
    return (uint32_t)__bfloat16_as_ushort(a) |
           ((uint32_t)__bfloat16_as_ushort(b) << 16);
}

// ---------------------------------------------------------------------------
// Engine A (fp32 inputs, split-on-load) — kPsi only.
// EPI=0: plain fp32 store. EPI=2: fp32 store + transposed hi/lo planes into
// btW ([gi][f]) for the pipelined W2 GEMM.
// ---------------------------------------------------------------------------
template<bool ATRANS, bool BTRANS, int NT, int EPI>
__global__ void __launch_bounds__(256) mmag_f(
    const float* __restrict__ A, const float* __restrict__ Bsrc,
    float* __restrict__ C,
    int lda, int ldb, int ldc, int Kreal, int Nreal, float alpha, int kchunks)
{
    constexpr int NT16 = NT / 16;
    __shared__ bf16 sA[2][128][40];
    __shared__ bf16 sB[2][NT][40];

    const int tid = threadIdx.x;
    const int r0 = blockIdx.y * 128;
    const int n0 = blockIdx.x * NT;
    const int lane = tid & 31, w = tid >> 5;
    const int wm = w & 3, wn = w >> 2;
    const int rA = wm * 32;
    const int nbase = wn * (NT / 2);

    float acc[2][NT16][4];
    #pragma unroll
    for (int mi = 0; mi < 2; mi++)
        #pragma unroll
        for (int ni = 0; ni < NT16; ni++)
            #pragma unroll
            for (int j = 0; j < 4; j++) acc[mi][ni][j] = 0.f;

    for (int ch = 0; ch < kchunks; ch++) {
        const int kc = ch * 32;
        __syncthreads();
        #pragma unroll
        for (int it = 0; it < 16; it++) {
            int idx = it * 256 + tid;
            int r, kk;
            if (ATRANS) { r = idx & 127; kk = idx >> 7; }
            else        { kk = idx & 31; r = idx >> 5;  }
            int gk = kc + kk;
            float v = 0.f;
            if (gk < Kreal)
                v = ATRANS ? A[(size_t)gk * lda + (r0 + r)]
                           : A[(size_t)(r0 + r) * lda + gk];
            split2(v, sA[0][r][kk], sA[1][r][kk]);
        }
        #pragma unroll
        for (int it = 0; it < NT / 8; it++) {
            int idx = it * 256 + tid;
            int n, kk;
            if (BTRANS) { n = idx & (NT - 1); kk = idx >> (NT == 128 ? 7 : 6); }
            else        { kk = idx & 31;      n = idx >> 5; }
            int gk = kc + kk, gn = n0 + n;
            float v = 0.f;
            if (gk < Kreal && gn < Nreal)
                v = BTRANS ? Bsrc[(size_t)gk * ldb + gn]
                           : Bsrc[(size_t)gn * ldb + gk];
            split2(v, sB[0][n][kk], sB[1][n][kk]);
        }
        __syncthreads();
        #pragma unroll
        for (int kk = 0; kk < 32; kk += 16) {
            uint32_t aH[2][4], aL[2][4];
            const int arow = rA + (lane & 7) + ((lane >> 3) & 1) * 8;
            const int akc  = kk + (lane >> 4) * 8;
            #pragma unroll
            for (int mi = 0; mi < 2; mi++) {
                ldsm4(smem_u32(&sA[0][arow + mi * 16][akc]), aH[mi]);
                ldsm4(smem_u32(&sA[1][arow + mi * 16][akc]), aL[mi]);
            }
            #pragma unroll
            for (int np = 0; np < NT16 / 2; np++) {
                uint32_t bH[4], bL[4];
                const int brow = nbase + np * 16 + (lane >> 4) * 8 + (lane & 7);
                const int bkc  = kk + ((lane >> 3) & 1) * 8;
                ldsm4(smem_u32(&sB[0][brow][bkc]), bH);
                ldsm4(smem_u32(&sB[1][brow][bkc]), bL);
                #pragma unroll
                for (int mi = 0; mi < 2; mi++) {
                    #pragma unroll
                    for (int h = 0; h < 2; h++) {
                        int ni = 2 * np + h;
                        mma16816(acc[mi][ni], aH[mi], &bH[2 * h]);
                        mma16816(acc[mi][ni], aH[mi], &bL[2 * h]);
                        mma16816(acc[mi][ni], aL[mi], &bH[2 * h]);
                    }
                }
            }
        }
    }

    const int g2 = lane >> 2, tg = lane & 3;
    #pragma unroll
    for (int mi = 0; mi < 2; mi++) {
        #pragma unroll
        for (int ni = 0; ni < NT16; ni++) {
            int row = r0 + rA + mi * 16 + g2;
            int col = n0 + nbase + ni * 8 + tg * 2;
            #pragma unroll
            for (int j = 0; j < 4; j++) {
                int rr = row + (j >> 1) * 8;
                int nn = col + (j & 1);
                if (nn < Nreal) {
                    float v = alpha * acc[mi][ni][j];
                    C[(size_t)rr * ldc + nn] = v;
                    if (EPI == 2) {
                        // psi[fg][i] -> btW[g*49+i][f]
                        int f = rr >> 3, g = rr & 7;
                        size_t o = (size_t)(g * S2 + nn) * 512 + f;
                        bf16 h, lo;
                        split2(v, h, lo);
                        d_btWh[o] = h;
                        d_btWl[o] = lo;
                    }
                }
            }
        }
    }
}

// ---------------------------------------------------------------------------
// Specialized AD kernel: AD[i][bc] = sum_hw fmap[bc][hw] * P[hw][i]
// SMEM-staged coalesced transposed plane stores. grid.x = 2048.
// ---------------------------------------------------------------------------
__global__ void __launch_bounds__(256) kAD_kernel(
    const float* __restrict__ A, bf16* __restrict__ Ch, bf16* __restrict__ Cl)
{
    __shared__ __align__(16) char smr[30720];
    bf16 (*sA)[128][40] = reinterpret_cast<bf16(*)[128][40]>(smr);
    bf16 (*sB)[64][40]  = reinterpret_cast<bf16(*)[64][40]>(smr + 20480);

    const int tid = threadIdx.x;
    const int r0 = blockIdx.x * 128;
    const int lane = tid & 31, w = tid >> 5;
    const int rA = (w & 3) * 32;
    const int nbase = (w >> 2) * 32;

    float acc[2][4][4];
    #pragma unroll
    for (int mi = 0; mi < 2; mi++)
        #pragma unroll
        for (int ni = 0; ni < 4; ni++)
            #pragma unroll
            for (int j = 0; j < 4; j++) acc[mi][ni][j] = 0.f;

    for (int ch = 0; ch < 2; ch++) {
        const int kc = ch * 32;
        __syncthreads();
        #pragma unroll
        for (int it = 0; it < 16; it++) {
            int idx = it * 256 + tid;
            int kk = idx & 31, r = idx >> 5;
            int gk = kc + kk;
            float v = (gk < HW) ? A[(size_t)(r0 + r) * HW + gk] : 0.f;
            split2(v, sA[0][r][kk], sA[1][r][kk]);
        }
        #pragma unroll
        for (int it = 0; it < 8; it++) {
            int idx = it * 256 + tid;
            int n = idx & 63, kk = idx >> 6;
            int gk = kc + kk;
            float v = (gk < HW && n < S2) ? d_P[gk * S2 + n] : 0.f;
            split2(v, sB[0][n][kk], sB[1][n][kk]);
        }
        __syncthreads();
        #pragma unroll
        for (int kk = 0; kk < 32; kk += 16) {
            uint32_t aH[2][4], aL[2][4];
            const int arow = rA + (lane & 7) + ((lane >> 3) & 1) * 8;
            const int akc  = kk + (lane >> 4) * 8;
            #pragma unroll
            for (int mi = 0; mi < 2; mi++) {
                ldsm4(smem_u32(&sA[0][arow + mi * 16][akc]), aH[mi]);
                ldsm4(smem_u32(&sA[1][arow + mi * 16][akc]), aL[mi]);
            }
            #pragma unroll
            for (int np = 0; np < 2; np++) {
                uint32_t bH[4], bL[4];
                const int brow = nbase + np * 16 + (lane >> 4) * 8 + (lane & 7);
                const int bkc  = kk + ((lane >> 3) & 1) * 8;
                ldsm4(smem_u32(&sB[0][brow][bkc]), bH);
                ldsm4(smem_u32(&sB[1][brow][bkc]), bL);
                #pragma unroll
                for (int mi = 0; mi < 2; mi++) {
                    #pragma unroll
                    for (int h = 0; h < 2; h++) {
                        int ni = 2 * np + h;
                        mma16816(acc[mi][ni], aH[mi], &bH[2 * h]);
                        mma16816(acc[mi][ni], aH[mi], &bL[2 * h]);
                        mma16816(acc[mi][ni], aL[mi], &bH[2 * h]);
                    }
                }
            }
        }
    }

    __syncthreads();
    bf16 (*sH)[128] = reinterpret_cast<bf16(*)[128]>(smr);          // [49][128]
    bf16 (*sL)[128] = reinterpret_cast<bf16(*)[128]>(smr + 12800);
    const int g2 = lane >> 2, tg = lane & 3;
    #pragma unroll
    for (int mi = 0; mi < 2; mi++) {
        #pragma unroll
        for (int ni = 0; ni < 4; ni++) {
            int rowl = rA + mi * 16 + g2;
            int col = nbase + ni * 8 + tg * 2;
            #pragma unroll
            for (int j = 0; j < 4; j++) {
                int rr = rowl + (j >> 1) * 8;
                int nn = col + (j & 1);
                if (nn < S2) {
                    bf16 h, l;
                    split2(acc[mi][ni][j], h, l);
                    sH[nn][rr] = h;
                    sL[nn][rr] = l;
                }
            }
        }
    }
    __syncthreads();
    for (int idx = tid; idx < S2 * 128; idx += 256) {
        int i = idx >> 7, r = idx & 127;
        size_t o = (size_t)i * BC + r0 + r;
        Ch[o] = sH[i][r];
        Cl[o] = sL[i][r];
    }
}

// ---------------------------------------------------------------------------
// Engine B (pre-split bf16 planes, cp.async double-buffered).
// EPI: 0 = fp32 C store, 1 = packed hi/lo plane store, 2 = permuted W2t store.
// ---------------------------------------------------------------------------
template<bool RELU, int EPI, bool LSEL>
__global__ void __launch_bounds__(256, 2) mmag_p(
    const bf16* __restrict__ Ah, const bf16* __restrict__ Al,
    const bf16* __restrict__ Bh, const bf16* __restrict__ Bl,
    float* __restrict__ C, bf16* __restrict__ Ch, bf16* __restrict__ Cl,
    int lda, int ldb, int ldc, int Nreal, int npMaxIn,
    int kchunks, int kstride, int zdivisor, int kmax,
    size_t astride, size_t bstride, size_t cstride, size_t cstride2)
{
    extern __shared__ bf16 S[];   // sA[2buf][2pl][128][40] then sB same: 81920 B
    const int tid = threadIdx.x;
    const int z = blockIdx.z;
    const int batch = z / zdivisor;
    const int sub = z - batch * zdivisor;
    const bf16* Aph = Ah + (size_t)batch * astride;
    const bf16* Apl = Al + (size_t)batch * astride;
    const size_t boff = (LSEL ? (size_t)c_l_of_i[batch] : (size_t)batch) * bstride;
    const bf16* Bph = Bh + boff;
    const bf16* Bpl = Bl + boff;
    float* Cp = C + (size_t)batch * cstride + (size_t)sub * cstride2;
    const int kbeg = sub * kstride;
    const int nch = min(kchunks, (kmax - kbeg + 31) >> 5);
    const int r0 = blockIdx.y * 128;
    const int n0 = blockIdx.x * 128;
    const int lane = tid & 31, w = tid >> 5;
    const int rA = (w & 3) * 32;
    const int nbase = (w >> 2) * 64;
    const uint32_t sbase = smem_u32(S);
    constexpr uint32_t SBOFF = 2 * 2 * 128 * 40 * 2;   // bytes

    int npMax = npMaxIn;
    if (LSEL) {
        int d = 2 * c_l_of_i[batch] + 1;
        npMax = (8 * d + 31) >> 5;        // 1..4
    }

    float acc[2][8][4];
    #pragma unroll
    for (int mi = 0; mi < 2; mi++)
        #pragma unroll
        for (int ni = 0; ni < 8; ni++)
            #pragma unroll
            for (int j = 0; j < 4; j++) acc[mi][ni][j] = 0.f;

    auto copyin = [&](int buf, int kc) {
        #pragma unroll
        for (int it = 0; it < 8; it++) {
            int idx = it * 256 + tid;
            int q = idx & 7, r = (idx >> 3) & 127, p = idx >> 10;
            const bf16* g = (p ? Apl : Aph) + (size_t)(r0 + r) * lda + kc + q * 4;
            uint32_t d = sbase + (((buf * 2 + p) * 128 + r) * 40 + q * 4) * 2;
            asm volatile("cp.async.ca.shared.global [%0], [%1], 8;"
                         :: "r"(d), "l"(g));
        }
        for (int p = 0; p < 2; p++) {
            for (int itn = 0; itn < npMax; itn++) {
                int q = tid & 7, r = itn * 32 + (tid >> 3);
                const bf16* g = (p ? Bpl : Bph) + (size_t)(n0 + r) * ldb + kc + q * 4;
                uint32_t d = sbase + SBOFF + (((buf * 2 + p) * 128 + r) * 40 + q * 4) * 2;
                asm volatile("cp.async.ca.shared.global [%0], [%1], 8;"
                             :: "r"(d), "l"(g));
            }
        }
        asm volatile("cp.async.commit_group;" ::: "memory");
    };

    int buf = 0;
    copyin(0, kbeg);

    for (int ch = 0; ch < nch; ch++) {
        if (ch + 1 < nch) {
            copyin(buf ^ 1, kbeg + (ch + 1) * 32);
            asm volatile("cp.async.wait_group 1;" ::: "memory");
        } else {
            asm volatile("cp.async.wait_group 0;" ::: "memory");
        }
        __syncthreads();

        #pragma unroll
        for (int kk = 0; kk < 32; kk += 16) {
            uint32_t aH[2][4], aL[2][4];
            const int arow = rA + (lane & 7) + ((lane >> 3) & 1) * 8;
            const int akc  = kk + (lane >> 4) * 8;
            #pragma unroll
            for (int mi = 0; mi < 2; mi++) {
                uint32_t a0 = sbase + (((buf * 2 + 0) * 128 + arow + mi * 16) * 40 + akc) * 2;
                uint32_t a1 = sbase + (((buf * 2 + 1) * 128 + arow + mi * 16) * 40 + akc) * 2;
                ldsm4(a0, aH[mi]);
                ldsm4(a1, aL[mi]);
            }
            #pragma unroll
            for (int np = 0; np < 4; np++) {
                if ((nbase >> 4) + np < (npMax << 1)) {
                    uint32_t bH[4], bL[4];
                    const int brow = nbase + np * 16 + (lane >> 4) * 8 + (lane & 7);
                    const int bkc  = kk + ((lane >> 3) & 1) * 8;
                    uint32_t b0 = sbase + SBOFF + (((buf * 2 + 0) * 128 + brow) * 40 + bkc) * 2;
                    uint32_t b1 = sbase + SBOFF + (((buf * 2 + 1) * 128 + brow) * 40 + bkc) * 2;
                    ldsm4(b0, bH);
                    ldsm4(b1, bL);
                    #pragma unroll
                    for (int mi = 0; mi < 2; mi++) {
                        #pragma unroll
                        for (int h = 0; h < 2; h++) {
                            int ni = 2 * np + h;
                            mma16816(acc[mi][ni], aH[mi], &bH[2 * h]);
                            mma16816(acc[mi][ni], aH[mi], &bL[2 * h]);
                            mma16816(acc[mi][ni], aL[mi], &bH[2 * h]);
                        }
                    }
                }
            }
        }
        __syncthreads();
        buf ^= 1;
    }

    const int g2 = lane >> 2, tg = lane & 3;
    #pragma unroll
    for (int mi = 0; mi < 2; mi++) {
        #pragma unroll
        for (int ni = 0; ni < 8; ni++) {
            if (((nbase + ni * 8) >> 5) >= npMax) continue;
            int row = r0 + rA + mi * 16 + g2;
            int col = n0 + nbase + ni * 8 + tg * 2;
            float v[4];
            #pragma unroll
            for (int j = 0; j < 4; j++) {
                v[j] = acc[mi][ni][j];
                if (RELU) v[j] = fmaxf(v[j], 0.f);
            }
            if (EPI == 1) {
                #pragma unroll
                for (int h = 0; h < 2; h++) {
                    int rr = row + h * 8;
                    bf16 h0, l0, h1, l1;
                    split2(v[2 * h + 0], h0, l0);
                    split2(v[2 * h + 1], h1, l1);
                    *(uint32_t*)&Ch[(size_t)rr * ldc + col] = pack2(h0, h1);
                    *(uint32_t*)&Cl[(size_t)rr * ldc + col] = pack2(l0, l1);
                }
            } else if (EPI == 2) {
                #pragma unroll
                for (int j = 0; j < 4; j++) {
                    int rr = row + (j >> 1) * 8;
                    int nn = col + (j & 1);
                    if (nn < Nreal) {
                        int g = nn / S2, i = nn - g * S2;
                        int l = c_l_of_i[i];
                        int u = i - l * l;
                        int jj = g * (2 * l + 1) + u;
                        size_t o = ((size_t)l * 128 + jj) * C_ + rr;
                        bf16 h, lo;
                        split2(v[j], h, lo);
                        d_W2th[o] = h;
                        d_W2tl[o] = lo;
                    }
                }
            } else {
                #pragma unroll
                for (int j = 0; j < 4; j++) {
                    int rr = row + (j >> 1) * 8;
                    int nn = col + (j & 1);
                    if (nn < Nreal) Cp[(size_t)rr * ldc + nn] = v[j];
                }
            }
        }
    }
}

// ---------------------------------------------------------------------------
// Small kernels
// ---------------------------------------------------------------------------
__global__ void k_Pq(const float* __restrict__ proj_w, const float* __restrict__ proj_Y) {
    const int tid = threadIdx.x;
    for (int t = tid; t < HW * S2; t += 256) {
        int hw = t / S2, i = t % S2;
        const float* wr = proj_w + hw * NP;
        float acc = 0.f;
        #pragma unroll 8
        for (int n = 0; n < NP; n++) acc += wr[n] * proj_Y[n * S2 + i];
        d_P[t] = acc * RS192;
    }
    __syncthreads();
    if (tid < S2) {
        float a = 0.f;
        for (int hw = 0; hw < HW; hw++) a += d_P[hw * S2 + tid];
        d_q[tid] = a;
    }
}

__global__ void k_bpsi(const float* __restrict__ conv_b) {
    __shared__ float part[8][33];
    const int lane = threadIdx.x & 31, w = threadIdx.x >> 5;
    const int t = blockIdx.x * 32 + lane;
    float acc = 0.f;
    if (t < GI) {
        #pragma unroll 8
        for (int ff = 0; ff < 64; ff++) {
            int f = w * 64 + ff;
            acc += conv_b[f] * d_psi[f * GI + t];
        }
    }
    part[w][lane] = acc;
    __syncthreads();
    if (w == 0 && t < GI) {
        float s = 0.f;
        #pragma unroll
        for (int j = 0; j < 8; j++) s += part[j][lane];
        d_bpsi[t] = s * RS512;
    }
}

__global__ void k_psi2(const float* __restrict__ so3_w, const float* __restrict__ so3_D) {
    int w = (blockIdx.x * blockDim.x + threadIdx.x) >> 5;
    int lane = threadIdx.x & 31;
    if (w >= G_ * SO3) return;
    int f = w / SO3, i = w % SO3;
    float acc = 0.f;
    for (int n = lane; n < NP; n += 32) acc += so3_w[f * NP + n] * so3_D[n * SO3 + i];
    #pragma unroll
    for (int o = 16; o; o >>= 1) acc += __shfl_xor_sync(0xFFFFFFFFu, acc, o);
    if (lane == 0) d_psi2[w] = acc * RS192;
}

// tiled transpose + scale + hi/lo split: out[n][k] = alpha * in[k][n]
__global__ void k_tpose(const float* __restrict__ in, bf16* __restrict__ oh,
                        bf16* __restrict__ ol, int inR, int inC, int ldo,
                        float alpha) {
    __shared__ float tl[32][33];
    int n0 = blockIdx.x * 32, k0 = blockIdx.y * 32;
    #pragma unroll
    for (int j = 0; j < 4; j++) {
        int k = k0 + threadIdx.y + j * 8, n = n0 + threadIdx.x;
        tl[threadIdx.y + j * 8][threadIdx.x] =
            (k < inR && n < inC) ? in[(size_t)k * inC + n] : 0.f;
    }
    __syncthreads();
    #pragma unroll
    for (int j = 0; j < 4; j++) {
        int n = n0 + threadIdx.y + j * 8, k = k0 + threadIdx.x;
        bf16 h, l;
        split2(alpha * tl[threadIdx.x][threadIdx.y + j * 8], h, l);
        oh[(size_t)n * ldo + k] = h;
        ol[(size_t)n * ldo + k] = l;
    }
}

// partD (6 k-slabs) + bias -> x4 planes [1024][512]
__global__ void k_x4() {
    int t = blockIdx.x * blockDim.x + threadIdx.x;
    if (t >= 1024 * 512) return;
    int row = t >> 9, col = t & 511;
    int b = row >> 3, g = row & 7;
    float v = 0.f;
    if (col < SO3) {
        int l = 6;
        while (col < c_off2[l]) l--;
        int d = 2 * l + 1, r = col - c_off2[l];
        int u = r / d, m = r - u * d, i = l * l + m;
        size_t o = (size_t)i * 128 * 104 + (size_t)b * 104 + g * d + u;
        float s = 0.f;
        #pragma unroll
        for (int zz = 0; zz < 6; zz++)
            s += d_partD[o + (size_t)zz * 49 * 128 * 104];
        v = s + d_bpsi[g * S2 + l * l + u] * d_q[l * l + m];
    }
    bf16 h, lo;
    split2(v, h, lo);
    d_x4h[t] = h;
    d_x4l[t] = lo;
}

__global__ void k_red6() {
    int t = blockIdx.x * blockDim.x + threadIdx.x;
    if (t >= 1024 * SO3) return;
    int row = t / SO3, col = t - row * SO3;
    float s = 0.f;
    #pragma unroll
    for (int zz = 0; zz < 8; zz++)
        s += d_part6[(size_t)zz * 1024 * 512 + (size_t)row * 512 + col];
    d_x5[t] = s;
}

__global__ void stageH_kernel(float* __restrict__ out) {
    int t = blockIdx.x * blockDim.x + threadIdx.x;
    if (t >= B_ * SO3) return;
    int b = t / SO3, j = t - b * SO3;
    int l = 6;
    while (j < c_off2[l]) l--;
    int d = 2 * l + 1;
    int r = j - c_off2[l];
    int v = r / d, m = r - v * d;
    float acc = 0.f;
    #pragma unroll
    for (int f = 0; f < G_; f++) {
        const float* xr = d_x5 + (size_t)(b * G_ + f) * SO3 + c_off2[l];
        const float* pr = d_psi2 + f * SO3 + c_off2[l];
        for (int u = 0; u < d; u++) acc += xr[u * d + m] * pr[u * d + v];
    }
    out[t] = acc * (1.0f / sqrtf(8.0f * d));
}

// ---------------------------------------------------------------------------
// Host launcher — multi-stream fork/join (capture-legal via events)
// ---------------------------------------------------------------------------
extern "C" void kernel_launch(void* const* d_in, const int* in_sizes, int n_in,
                              void* d_out, int out_size) {
    const float* fmap     = (const float*)d_in[0];
    const float* conv_w   = (const float*)d_in[1];
    const float* conv_b   = (const float*)d_in[2];
    const float* proj_w   = (const float*)d_in[3];
    const float* proj_Y   = (const float*)d_in[4];
    const float* fs_w     = (const float*)d_in[5];
    const float* fs_Y     = (const float*)d_in[6];
    const float* act_to   = (const float*)d_in[7];
    const float* act_from = (const float*)d_in[8];
    const float* so3_w    = (const float*)d_in[9];
    const float* so3_D    = (const float*)d_in[10];
    float* out = (float*)d_out;

    float *pPsi, *pPartD, *pPart6;
    bf16 *pADh, *pADl, *pW2th, *pW2tl, *pX4h, *pX4l, *pB5h, *pB5l;
    bf16 *pGh, *pGl, *pB6h, *pB6l, *pCwh, *pCwl, *pBWh, *pBWl;
    cudaGetSymbolAddress((void**)&pPsi,   d_psi);
    cudaGetSymbolAddress((void**)&pPartD, d_partD);
    cudaGetSymbolAddress((void**)&pPart6, d_part6);
    cudaGetSymbolAddress((void**)&pADh,   d_ADh);
    cudaGetSymbolAddress((void**)&pADl,   d_ADl);
    cudaGetSymbolAddress((void**)&pW2th,  d_W2th);
    cudaGetSymbolAddress((void**)&pW2tl,  d_W2tl);
    cudaGetSymbolAddress((void**)&pX4h,   d_x4h);
    cudaGetSymbolAddress((void**)&pX4l,   d_x4l);
    cudaGetSymbolAddress((void**)&pB5h,   d_bt5h);
    cudaGetSymbolAddress((void**)&pB5l,   d_bt5l);
    cudaGetSymbolAddress((void**)&pGh,    d_gacth);
    cudaGetSymbolAddress((void**)&pGl,    d_gactl);
    cudaGetSymbolAddress((void**)&pB6h,   d_bt6h);
    cudaGetSymbolAddress((void**)&pB6l,   d_bt6l);
    cudaGetSymbolAddress((void**)&pCwh,   d_cwTh);
    cudaGetSymbolAddress((void**)&pCwl,   d_cwTl);
    cudaGetSymbolAddress((void**)&pBWh,   d_btWh);
    cudaGetSymbolAddress((void**)&pBWl,   d_btWl);

    auto* kPsi = mmag_f<false, true, 64, 2>;
    auto* kW2p = mmag_p<false, 2, false>;
    auto* kSD  = mmag_p<false, 0, true >;
    auto* kS5  = mmag_p<true,  1, false>;
    auto* kS6  = mmag_p<false, 0, false>;
    constexpr int SMP = 2 * 2 * 2 * 128 * 40 * 2;   // 81920 B
    cudaFuncSetAttribute(kW2p, cudaFuncAttributeMaxDynamicSharedMemorySize, SMP);
    cudaFuncSetAttribute(kSD,  cudaFuncAttributeMaxDynamicSharedMemorySize, SMP);
    cudaFuncSetAttribute(kS5,  cudaFuncAttributeMaxDynamicSharedMemorySize, SMP);
    cudaFuncSetAttribute(kS6,  cudaFuncAttributeMaxDynamicSharedMemorySize, SMP);

    // one-time host-side infra (no device memory, identical GPU work per call)
    static cudaStream_t s1 = nullptr, s2 = nullptr;
    static cudaEvent_t evRoot = nullptr, evW2 = nullptr, evBps = nullptr, evAux = nullptr;
    if (s1 == nullptr) {
        cudaStreamCreateWithFlags(&s1, cudaStreamNonBlocking);
        cudaStreamCreateWithFlags(&s2, cudaStreamNonBlocking);
        cudaEventCreateWithFlags(&evRoot, cudaEventDisableTiming);
        cudaEventCreateWithFlags(&evW2,   cudaEventDisableTiming);
        cudaEventCreateWithFlags(&evBps,  cudaEventDisableTiming);
        cudaEventCreateWithFlags(&evAux,  cudaEventDisableTiming);
    }

    // fork: s1 (W2 chain), s2 (operand preps) join the capture via evRoot
    cudaEventRecord(evRoot, 0);
    cudaStreamWaitEvent(s1, evRoot, 0);
    cudaStreamWaitEvent(s2, evRoot, 0);

    // main chain
    k_Pq<<<1, 256>>>(proj_w, proj_Y);
    kAD_kernel<<<2048, 256>>>(fmap, pADh, pADl);

    // s1: conv_w^T planes (RS512 folded)  ||  psi (+ btW planes)  ->  W2 -> bpsi
    k_tpose<<<dim3(64, 16), dim3(32, 8), 0, s1>>>(conv_w, pCwh, pCwl,
                                                  FIN, C_, 512, RS512);
    kPsi<<<dim3(1, 32, 1), 256, 0, s1>>>(fs_w, fs_Y, pPsi,
                                         NP, S2, S2, NP, S2, RS192, 6);
    // W2 (pipelined): M=2048, N=392(512 pad), K=512 -> permuted W2t store
    kW2p<<<dim3(4, 16, 1), 256, SMP, s1>>>(pCwh, pCwl, pBWh, pBWl,
        (float*)0, (bf16*)0, (bf16*)0,
        512, 512, 0, GI, 4, 16, 512, 1, 512, 0, 0, 0, 0);
    cudaEventRecord(evW2, s1);
    k_bpsi<<<(GI + 31) / 32, 256, 0, s1>>>(conv_b);
    cudaEventRecord(evBps, s1);

    cudaStreamWaitEvent(0, evW2, 0);
    // stageD: 49 batches (M=128, N=8d, K=2048), split-K x6 -> 294 CTAs (1 wave)
    kSD<<<dim3(1, 1, 294), 256, SMP>>>(pADh, pADl, pW2th, pW2tl,
        pPartD, (bf16*)0, (bf16*)0,
        C_, C_, 104, 104, 4, 11, 352, 6, C_,
        BC, (size_t)128 * C_, (size_t)128 * 104, (size_t)49 * 128 * 104);

    // s2: operand preps (graph DAG: run concurrently with kAD/kSD)
    k_psi2<<<(G_ * SO3 * 32 + 127) / 128, 128, 0, s2>>>(so3_w, so3_D);
    k_tpose<<<dim3(128, 15), dim3(32, 8), 0, s2>>>(act_to,   pB5h, pB5l,
                                                   SO3, NG, 480, 1.f);
    k_tpose<<<dim3(16, 128), dim3(32, 8), 0, s2>>>(act_from, pB6h, pB6l,
                                                   NG, SO3, 4096, 1.f);
    cudaEventRecord(evAux, s2);

    cudaStreamWaitEvent(0, evBps, 0);
    k_x4<<<(1024 * 512 + 255) / 256, 256>>>();

    cudaStreamWaitEvent(0, evAux, 0);
    // stage5: gact planes = relu(x4 @ act_to)  (M=1024, N=4096, K=480)
    kS5<<<dim3(32, 8, 1), 256, SMP>>>(pX4h, pX4l, pB5h, pB5l,
        (float*)0, pGh, pGl,
        512, 480, 4096, 4096, 4, 15, 480, 1, 480, 0, 0, 0, 0);

    // stage6: part6[z] = gact @ act_from  (M=1024, N=512, K=4096), split-K x8
    kS6<<<dim3(4, 8, 8), 256, SMP>>>(pGh, pGl, pB6h, pB6l,
        pPart6, (bf16*)0, (bf16*)0,
        4096, 4096, 512, 512, 4, 16, 512, 8, 4096,
        0, 0, 0, (size_t)1024 * 512);
    k_red6<<<(1024 * SO3 + 255) / 256, 256>>>();

    stageH_kernel<<<(B_ * SO3 + 255) / 256, 256>>>(out);
}

// round 17
// speedup vs baseline: 1.0500x; 1.0500x over previous
#include <cuda_runtime.h>
#include <cuda_bf16.h>
#include <math.h>
#include <stdint.h>

typedef __nv_bfloat16 bf16;

// ---------------------------------------------------------------------------
// Problem constants
// ---------------------------------------------------------------------------
static constexpr int B_   = 128;
static constexpr int C_   = 2048;
static constexpr int HW   = 49;
static constexpr int FIN  = 512;
static constexpr int G_   = 8;
static constexpr int NP   = 192;
static constexpr int S2   = 49;
static constexpr int SO3  = 455;
static constexpr int NG   = 4000;
static constexpr int GI   = 392;                // G_*S2
static constexpr size_t BC = (size_t)B_ * C_;   // 262144

static constexpr float RS192 = 0.07216878364870323f;
static constexpr float RS512 = 0.04419417382415922f;

// ---------------------------------------------------------------------------
// Scratch (device globals; runtime allocation is forbidden)
// ---------------------------------------------------------------------------
__device__ float d_P[HW * S2];
__device__ float d_q[S2];
__device__ float d_psi[FIN * GI];
__device__ float d_bpsi[GI];
__device__ float d_psi2[G_ * SO3];

// hi/lo bf16 planes (pre-split operands for the pipelined GEMMs)
__device__ __align__(16) bf16 d_ADh[(size_t)49 * BC];   // [i][b*2048+c]
__device__ __align__(16) bf16 d_ADl[(size_t)49 * BC];
// W2t planes: pad rows (j >= 8d) are NEVER written -> stay zero-initialized.
__device__ __align__(16) bf16 d_W2th[7 * 128 * C_];     // [l][j pad128][c]
__device__ __align__(16) bf16 d_W2tl[7 * 128 * C_];
// conv_w^T planes (RS512 folded) and psi^T planes for the pipelined W2 GEMM
__device__ __align__(16) bf16 d_cwTh[C_ * 512];         // [c][f]
__device__ __align__(16) bf16 d_cwTl[C_ * 512];
__device__ __align__(16) bf16 d_btWh[512 * 512];        // [gi pad512][f] (pad rows zero)
__device__ __align__(16) bf16 d_btWl[512 * 512];
__device__ __align__(16) bf16 d_x4h[1024 * 512];        // [b*8+g][so3 pad512]
__device__ __align__(16) bf16 d_x4l[1024 * 512];
__device__ __align__(16) bf16 d_bt5h[(size_t)4096 * 480]; // act_to^T planes
__device__ __align__(16) bf16 d_bt5l[(size_t)4096 * 480];
__device__ __align__(16) bf16 d_gacth[(size_t)1024 * 4096];
__device__ __align__(16) bf16 d_gactl[(size_t)1024 * 4096];
__device__ __align__(16) bf16 d_bt6h[(size_t)512 * 4096]; // act_from^T planes
__device__ __align__(16) bf16 d_bt6l[(size_t)512 * 4096];

__device__ float d_partD[(size_t)6 * 49 * 128 * 104];
__device__ float d_part6[(size_t)8 * 1024 * 512];
__device__ float d_x5[1024 * SO3];

__constant__ int c_off2[8] = {0, 1, 10, 35, 84, 165, 286, 455};
__constant__ int c_l_of_i[49] = {
    0, 1,1,1, 2,2,2,2,2, 3,3,3,3,3,3,3, 4,4,4,4,4,4,4,4,4,
    5,5,5,5,5,5,5,5,5,5,5, 6,6,6,6,6,6,6,6,6,6,6,6,6};

// ---------------------------------------------------------------------------
// helpers
// ---------------------------------------------------------------------------
__device__ __forceinline__ uint32_t smem_u32(const void* p) {
    uint32_t a;
    asm("{ .reg .u64 t; cvta.to.shared.u64 t, %1; cvt.u32.u64 %0, t; }"
        : "=r"(a) : "l"(p));
    return a;
}

__device__ __forceinline__ void ldsm4(uint32_t addr, uint32_t r[4]) {
    asm volatile("ldmatrix.sync.aligned.m8n8.x4.shared.b16 {%0,%1,%2,%3}, [%4];"
                 : "=r"(r[0]), "=r"(r[1]), "=r"(r[2]), "=r"(r[3]) : "r"(addr));
}

__device__ __forceinline__ void mma16816(float c[4], const uint32_t a[4],
                                         const uint32_t b[2]) {
    asm volatile(
        "mma.sync.aligned.m16n8k16.row.col.f32.bf16.bf16.f32 "
        "{%0,%1,%2,%3}, {%4,%5,%6,%7}, {%8,%9}, {%0,%1,%2,%3};"
        : "+f"(c[0]), "+f"(c[1]), "+f"(c[2]), "+f"(c[3])
        : "r"(a[0]), "r"(a[1]), "r"(a[2]), "r"(a[3]), "r"(b[0]), "r"(b[1]));
}

__device__ __forceinline__ void split2(float v, bf16& h, bf16& l) {
    h = __float2bfloat16(v);
    l = __float2bfloat16(v - __bfloat162float(h));
}

__device__ __forceinline__ uint32_t pack2(bf16 a, bf16 b) {
    return (uint32_t)__bfloat16_as_ushort(a) |
           ((uint32_t)__bfloat16_as_ushort(b) << 16);
}

// ---------------------------------------------------------------------------
// Engine A (fp32 inputs, split-on-load) — kPsi only (plain fp32 epilogue).
// ---------------------------------------------------------------------------
template<bool ATRANS, bool BTRANS, int NT>
__global__ void __launch_bounds__(256) mmag_f(
    const float* __restrict__ A, const float* __restrict__ Bsrc,
    float* __restrict__ C,
    int lda, int ldb, int ldc, int Kreal, int Nreal, float alpha, int kchunks)
{
    constexpr int NT16 = NT / 16;
    __shared__ bf16 sA[2][128][40];
    __shared__ bf16 sB[2][NT][40];

    const int tid = threadIdx.x;
    const int r0 = blockIdx.y * 128;
    const int n0 = blockIdx.x * NT;
    const int lane = tid & 31, w = tid >> 5;
    const int wm = w & 3, wn = w >> 2;
    const int rA = wm * 32;
    const int nbase = wn * (NT / 2);

    float acc[2][NT16][4];
    #pragma unroll
    for (int mi = 0; mi < 2; mi++)
        #pragma unroll
        for (int ni = 0; ni < NT16; ni++)
            #pragma unroll
            for (int j = 0; j < 4; j++) acc[mi][ni][j] = 0.f;

    for (int ch = 0; ch < kchunks; ch++) {
        const int kc = ch * 32;
        __syncthreads();
        #pragma unroll
        for (int it = 0; it < 16; it++) {
            int idx = it * 256 + tid;
            int r, kk;
            if (ATRANS) { r = idx & 127; kk = idx >> 7; }
            else        { kk = idx & 31; r = idx >> 5;  }
            int gk = kc + kk;
            float v = 0.f;
            if (gk < Kreal)
                v = ATRANS ? A[(size_t)gk * lda + (r0 + r)]
                           : A[(size_t)(r0 + r) * lda + gk];
            split2(v, sA[0][r][kk], sA[1][r][kk]);
        }
        #pragma unroll
        for (int it = 0; it < NT / 8; it++) {
            int idx = it * 256 + tid;
            int n, kk;
            if (BTRANS) { n = idx & (NT - 1); kk = idx >> (NT == 128 ? 7 : 6); }
            else        { kk = idx & 31;      n = idx >> 5; }
            int gk = kc + kk, gn = n0 + n;
            float v = 0.f;
            if (gk < Kreal && gn < Nreal)
                v = BTRANS ? Bsrc[(size_t)gk * ldb + gn]
                           : Bsrc[(size_t)gn * ldb + gk];
            split2(v, sB[0][n][kk], sB[1][n][kk]);
        }
        __syncthreads();
        #pragma unroll
        for (int kk = 0; kk < 32; kk += 16) {
            uint32_t aH[2][4], aL[2][4];
            const int arow = rA + (lane & 7) + ((lane >> 3) & 1) * 8;
            const int akc  = kk + (lane >> 4) * 8;
            #pragma unroll
            for (int mi = 0; mi < 2; mi++) {
                ldsm4(smem_u32(&sA[0][arow + mi * 16][akc]), aH[mi]);
                ldsm4(smem_u32(&sA[1][arow + mi * 16][akc]), aL[mi]);
            }
            #pragma unroll
            for (int np = 0; np < NT16 / 2; np++) {
                uint32_t bH[4], bL[4];
                const int brow = nbase + np * 16 + (lane >> 4) * 8 + (lane & 7);
                const int bkc  = kk + ((lane >> 3) & 1) * 8;
                ldsm4(smem_u32(&sB[0][brow][bkc]), bH);
                ldsm4(smem_u32(&sB[1][brow][bkc]), bL);
                #pragma unroll
                for (int mi = 0; mi < 2; mi++) {
                    #pragma unroll
                    for (int h = 0; h < 2; h++) {
                        int ni = 2 * np + h;
                        mma16816(acc[mi][ni], aH[mi], &bH[2 * h]);
                        mma16816(acc[mi][ni], aH[mi], &bL[2 * h]);
                        mma16816(acc[mi][ni], aL[mi], &bH[2 * h]);
                    }
                }
            }
        }
    }

    const int g2 = lane >> 2, tg = lane & 3;
    #pragma unroll
    for (int mi = 0; mi < 2; mi++) {
        #pragma unroll
        for (int ni = 0; ni < NT16; ni++) {
            int row = r0 + rA + mi * 16 + g2;
            int col = n0 + nbase + ni * 8 + tg * 2;
            #pragma unroll
            for (int j = 0; j < 4; j++) {
                int rr = row + (j >> 1) * 8;
                int nn = col + (j & 1);
                if (nn < Nreal)
                    C[(size_t)rr * ldc + nn] = alpha * acc[mi][ni][j];
            }
        }
    }
}

// ---------------------------------------------------------------------------
// psi -> btW planes:  btW[g*49+i][f] = psi[(f*8+g)*49 + i]
// grid (8 g, 8 fchunk), block 256. smem tile [64 f][49 i].
// ---------------------------------------------------------------------------
__global__ void k_tposePsi() {
    __shared__ float tl[64][50];
    const int g = blockIdx.x;
    const int f0 = blockIdx.y * 64;
    const int tid = threadIdx.x;
    for (int idx = tid; idx < 64 * 49; idx += 256) {
        int fi = idx / 49, ii = idx - fi * 49;
        tl[fi][ii] = d_psi[(size_t)((f0 + fi) * 8 + g) * GI + g * 0 + 0];
        // NOTE: d_psi layout is [fg][i] with row length S2 per (f,g)? No:
        // d_psi is [FIN*GI] = [f][g][i] flattened as (f*8+g)*49+i.
        tl[fi][ii] = d_psi[(size_t)((f0 + fi) * 8 + g) * 49 + ii];
    }
    __syncthreads();
    for (int idx = tid; idx < 49 * 64; idx += 256) {
        int ii = idx >> 6, fi = idx & 63;
        bf16 h, l;
        split2(tl[fi][ii], h, l);
        size_t o = (size_t)(g * 49 + ii) * 512 + f0 + fi;
        d_btWh[o] = h;
        d_btWl[o] = l;
    }
}

// ---------------------------------------------------------------------------
// Specialized AD kernel: AD[i][bc] = sum_hw fmap[bc][hw] * P[hw][i]
// SMEM-staged coalesced transposed plane stores. grid.x = 2048.
// ---------------------------------------------------------------------------
__global__ void __launch_bounds__(256) kAD_kernel(
    const float* __restrict__ A, bf16* __restrict__ Ch, bf16* __restrict__ Cl)
{
    __shared__ __align__(16) char smr[30720];
    bf16 (*sA)[128][40] = reinterpret_cast<bf16(*)[128][40]>(smr);
    bf16 (*sB)[64][40]  = reinterpret_cast<bf16(*)[64][40]>(smr + 20480);

    const int tid = threadIdx.x;
    const int r0 = blockIdx.x * 128;
    const int lane = tid & 31, w = tid >> 5;
    const int rA = (w & 3) * 32;
    const int nbase = (w >> 2) * 32;

    float acc[2][4][4];
    #pragma unroll
    for (int mi = 0; mi < 2; mi++)
        #pragma unroll
        for (int ni = 0; ni < 4; ni++)
            #pragma unroll
            for (int j = 0; j < 4; j++) acc[mi][ni][j] = 0.f;

    for (int ch = 0; ch < 2; ch++) {
        const int kc = ch * 32;
        __syncthreads();
        #pragma unroll
        for (int it = 0; it < 16; it++) {
            int idx = it * 256 + tid;
            int kk = idx & 31, r = idx >> 5;
            int gk = kc + kk;
            float v = (gk < HW) ? A[(size_t)(r0 + r) * HW + gk] : 0.f;
            split2(v, sA[0][r][kk], sA[1][r][kk]);
        }
        #pragma unroll
        for (int it = 0; it < 8; it++) {
            int idx = it * 256 + tid;
            int n = idx & 63, kk = idx >> 6;
            int gk = kc + kk;
            float v = (gk < HW && n < S2) ? d_P[gk * S2 + n] : 0.f;
            split2(v, sB[0][n][kk], sB[1][n][kk]);
        }
        __syncthreads();
        #pragma unroll
        for (int kk = 0; kk < 32; kk += 16) {
            uint32_t aH[2][4], aL[2][4];
            const int arow = rA + (lane & 7) + ((lane >> 3) & 1) * 8;
            const int akc  = kk + (lane >> 4) * 8;
            #pragma unroll
            for (int mi = 0; mi < 2; mi++) {
                ldsm4(smem_u32(&sA[0][arow + mi * 16][akc]), aH[mi]);
                ldsm4(smem_u32(&sA[1][arow + mi * 16][akc]), aL[mi]);
            }
            #pragma unroll
            for (int np = 0; np < 2; np++) {
                uint32_t bH[4], bL[4];
                const int brow = nbase + np * 16 + (lane >> 4) * 8 + (lane & 7);
                const int bkc  = kk + ((lane >> 3) & 1) * 8;
                ldsm4(smem_u32(&sB[0][brow][bkc]), bH);
                ldsm4(smem_u32(&sB[1][brow][bkc]), bL);
                #pragma unroll
                for (int mi = 0; mi < 2; mi++) {
                    #pragma unroll
                    for (int h = 0; h < 2; h++) {
                        int ni = 2 * np + h;
                        mma16816(acc[mi][ni], aH[mi], &bH[2 * h]);
                        mma16816(acc[mi][ni], aH[mi], &bL[2 * h]);
                        mma16816(acc[mi][ni], aL[mi], &bH[2 * h]);
                    }
                }
            }
        }
    }

    __syncthreads();
    bf16 (*sH)[128] = reinterpret_cast<bf16(*)[128]>(smr);          // [49][128]
    bf16 (*sL)[128] = reinterpret_cast<bf16(*)[128]>(smr + 12800);
    const int g2 = lane >> 2, tg = lane & 3;
    #pragma unroll
    for (int mi = 0; mi < 2; mi++) {
        #pragma unroll
        for (int ni = 0; ni < 4; ni++) {
            int rowl = rA + mi * 16 + g2;
            int col = nbase + ni * 8 + tg * 2;
            #pragma unroll
            for (int j = 0; j < 4; j++) {
                int rr = rowl + (j >> 1) * 8;
                int nn = col + (j & 1);
                if (nn < S2) {
                    bf16 h, l;
                    split2(acc[mi][ni][j], h, l);
                    sH[nn][rr] = h;
                    sL[nn][rr] = l;
                }
            }
        }
    }
    __syncthreads();
    for (int idx = tid; idx < S2 * 128; idx += 256) {
        int i = idx >> 7, r = idx & 127;
        size_t o = (size_t)i * BC + r0 + r;
        Ch[o] = sH[i][r];
        Cl[o] = sL[i][r];
    }
}

// ---------------------------------------------------------------------------
// Engine B (pre-split bf16 planes, cp.async double-buffered).
// EPI: 0 = fp32 C store, 1 = packed hi/lo plane store, 2 = permuted W2t store.
// ---------------------------------------------------------------------------
template<bool RELU, int EPI, bool LSEL>
__global__ void __launch_bounds__(256, 2) mmag_p(
    const bf16* __restrict__ Ah, const bf16* __restrict__ Al,
    const bf16* __restrict__ Bh, const bf16* __restrict__ Bl,
    float* __restrict__ C, bf16* __restrict__ Ch, bf16* __restrict__ Cl,
    int lda, int ldb, int ldc, int Nreal, int npMaxIn,
    int kchunks, int kstride, int zdivisor, int kmax,
    size_t astride, size_t bstride, size_t cstride, size_t cstride2)
{
    extern __shared__ bf16 S[];   // sA[2buf][2pl][128][40] then sB same: 81920 B
    const int tid = threadIdx.x;
    const int z = blockIdx.z;
    const int batch = z / zdivisor;
    const int sub = z - batch * zdivisor;
    const bf16* Aph = Ah + (size_t)batch * astride;
    const bf16* Apl = Al + (size_t)batch * astride;
    const size_t boff = (LSEL ? (size_t)c_l_of_i[batch] : (size_t)batch) * bstride;
    const bf16* Bph = Bh + boff;
    const bf16* Bpl = Bl + boff;
    float* Cp = C + (size_t)batch * cstride + (size_t)sub * cstride2;
    const int kbeg = sub * kstride;
    const int nch = min(kchunks, (kmax - kbeg + 31) >> 5);
    const int r0 = blockIdx.y * 128;
    const int n0 = blockIdx.x * 128;
    const int lane = tid & 31, w = tid >> 5;
    const int rA = (w & 3) * 32;
    const int nbase = (w >> 2) * 64;
    const uint32_t sbase = smem_u32(S);
    constexpr uint32_t SBOFF = 2 * 2 * 128 * 40 * 2;   // bytes

    int npMax = npMaxIn;
    if (LSEL) {
        int d = 2 * c_l_of_i[batch] + 1;
        npMax = (8 * d + 31) >> 5;        // 1..4
    }

    float acc[2][8][4];
    #pragma unroll
    for (int mi = 0; mi < 2; mi++)
        #pragma unroll
        for (int ni = 0; ni < 8; ni++)
            #pragma unroll
            for (int j = 0; j < 4; j++) acc[mi][ni][j] = 0.f;

    auto copyin = [&](int buf, int kc) {
        #pragma unroll
        for (int it = 0; it < 8; it++) {
            int idx = it * 256 + tid;
            int q = idx & 7, r = (idx >> 3) & 127, p = idx >> 10;
            const bf16* g = (p ? Apl : Aph) + (size_t)(r0 + r) * lda + kc + q * 4;
            uint32_t d = sbase + (((buf * 2 + p) * 128 + r) * 40 + q * 4) * 2;
            asm volatile("cp.async.ca.shared.global [%0], [%1], 8;"
                         :: "r"(d), "l"(g));
        }
        for (int p = 0; p < 2; p++) {
            for (int itn = 0; itn < npMax; itn++) {
                int q = tid & 7, r = itn * 32 + (tid >> 3);
                const bf16* g = (p ? Bpl : Bph) + (size_t)(n0 + r) * ldb + kc + q * 4;
                uint32_t d = sbase + SBOFF + (((buf * 2 + p) * 128 + r) * 40 + q * 4) * 2;
                asm volatile("cp.async.ca.shared.global [%0], [%1], 8;"
                             :: "r"(d), "l"(g));
            }
        }
        asm volatile("cp.async.commit_group;" ::: "memory");
    };

    int buf = 0;
    copyin(0, kbeg);

    for (int ch = 0; ch < nch; ch++) {
        if (ch + 1 < nch) {
            copyin(buf ^ 1, kbeg + (ch + 1) * 32);
            asm volatile("cp.async.wait_group 1;" ::: "memory");
        } else {
            asm volatile("cp.async.wait_group 0;" ::: "memory");
        }
        __syncthreads();

        #pragma unroll
        for (int kk = 0; kk < 32; kk += 16) {
            uint32_t aH[2][4], aL[2][4];
            const int arow = rA + (lane & 7) + ((lane >> 3) & 1) * 8;
            const int akc  = kk + (lane >> 4) * 8;
            #pragma unroll
            for (int mi = 0; mi < 2; mi++) {
                uint32_t a0 = sbase + (((buf * 2 + 0) * 128 + arow + mi * 16) * 40 + akc) * 2;
                uint32_t a1 = sbase + (((buf * 2 + 1) * 128 + arow + mi * 16) * 40 + akc) * 2;
                ldsm4(a0, aH[mi]);
                ldsm4(a1, aL[mi]);
            }
            #pragma unroll
            for (int np = 0; np < 4; np++) {
                if ((nbase >> 4) + np < (npMax << 1)) {
                    uint32_t bH[4], bL[4];
                    const int brow = nbase + np * 16 + (lane >> 4) * 8 + (lane & 7);
                    const int bkc  = kk + ((lane >> 3) & 1) * 8;
                    uint32_t b0 = sbase + SBOFF + (((buf * 2 + 0) * 128 + brow) * 40 + bkc) * 2;
                    uint32_t b1 = sbase + SBOFF + (((buf * 2 + 1) * 128 + brow) * 40 + bkc) * 2;
                    ldsm4(b0, bH);
                    ldsm4(b1, bL);
                    #pragma unroll
                    for (int mi = 0; mi < 2; mi++) {
                        #pragma unroll
                        for (int h = 0; h < 2; h++) {
                            int ni = 2 * np + h;
                            mma16816(acc[mi][ni], aH[mi], &bH[2 * h]);
                            mma16816(acc[mi][ni], aH[mi], &bL[2 * h]);
                            mma16816(acc[mi][ni], aL[mi], &bH[2 * h]);
                        }
                    }
                }
            }
        }
        __syncthreads();
        buf ^= 1;
    }

    const int g2 = lane >> 2, tg = lane & 3;
    #pragma unroll
    for (int mi = 0; mi < 2; mi++) {
        #pragma unroll
        for (int ni = 0; ni < 8; ni++) {
            if (((nbase + ni * 8) >> 5) >= npMax) continue;
            int row = r0 + rA + mi * 16 + g2;
            int col = n0 + nbase + ni * 8 + tg * 2;
            float v[4];
            #pragma unroll
            for (int j = 0; j < 4; j++) {
                v[j] = acc[mi][ni][j];
                if (RELU) v[j] = fmaxf(v[j], 0.f);
            }
            if (EPI == 1) {
                #pragma unroll
                for (int h = 0; h < 2; h++) {
                    int rr = row + h * 8;
                    bf16 h0, l0, h1, l1;
                    split2(v[2 * h + 0], h0, l0);
                    split2(v[2 * h + 1], h1, l1);
                    *(uint32_t*)&Ch[(size_t)rr * ldc + col] = pack2(h0, h1);
                    *(uint32_t*)&Cl[(size_t)rr * ldc + col] = pack2(l0, l1);
                }
            } else if (EPI == 2) {
                #pragma unroll
                for (int j = 0; j < 4; j++) {
                    int rr = row + (j >> 1) * 8;
                    int nn = col + (j & 1);
                    if (nn < Nreal) {
                        int g = nn / S2, i = nn - g * S2;
                        int l = c_l_of_i[i];
                        int u = i - l * l;
                        int jj = g * (2 * l + 1) + u;
                        size_t o = ((size_t)l * 128 + jj) * C_ + rr;
                        bf16 h, lo;
                        split2(v[j], h, lo);
                        d_W2th[o] = h;
                        d_W2tl[o] = lo;
                    }
                }
            } else {
                #pragma unroll
                for (int j = 0; j < 4; j++) {
                    int rr = row + (j >> 1) * 8;
                    int nn = col + (j & 1);
                    if (nn < Nreal) Cp[(size_t)rr * ldc + nn] = v[j];
                }
            }
        }
    }
}

// ---------------------------------------------------------------------------
// Small kernels
// ---------------------------------------------------------------------------
__global__ void k_Pq(const float* __restrict__ proj_w, const float* __restrict__ proj_Y) {
    const int tid = threadIdx.x;
    for (int t = tid; t < HW * S2; t += 256) {
        int hw = t / S2, i = t % S2;
        const float* wr = proj_w + hw * NP;
        float acc = 0.f;
        #pragma unroll 8
        for (int n = 0; n < NP; n++) acc += wr[n] * proj_Y[n * S2 + i];
        d_P[t] = acc * RS192;
    }
    __syncthreads();
    if (tid < S2) {
        float a = 0.f;
        for (int hw = 0; hw < HW; hw++) a += d_P[hw * S2 + tid];
        d_q[tid] = a;
    }
}

__global__ void k_bpsi(const float* __restrict__ conv_b) {
    __shared__ float part[8][33];
    const int lane = threadIdx.x & 31, w = threadIdx.x >> 5;
    const int t = blockIdx.x * 32 + lane;
    float acc = 0.f;
    if (t < GI) {
        #pragma unroll 8
        for (int ff = 0; ff < 64; ff++) {
            int f = w * 64 + ff;
            acc += conv_b[f] * d_psi[f * GI + t];
        }
    }
    part[w][lane] = acc;
    __syncthreads();
    if (w == 0 && t < GI) {
        float s = 0.f;
        #pragma unroll
        for (int j = 0; j < 8; j++) s += part[j][lane];
        d_bpsi[t] = s * RS512;
    }
}

__global__ void k_psi2(const float* __restrict__ so3_w, const float* __restrict__ so3_D) {
    int w = (blockIdx.x * blockDim.x + threadIdx.x) >> 5;
    int lane = threadIdx.x & 31;
    if (w >= G_ * SO3) return;
    int f = w / SO3, i = w % SO3;
    float acc = 0.f;
    for (int n = lane; n < NP; n += 32) acc += so3_w[f * NP + n] * so3_D[n * SO3 + i];
    #pragma unroll
    for (int o = 16; o; o >>= 1) acc += __shfl_xor_sync(0xFFFFFFFFu, acc, o);
    if (lane == 0) d_psi2[w] = acc * RS192;
}

// tiled transpose + scale + hi/lo split: out[n][k] = alpha * in[k][n]
__global__ void k_tpose(const float* __restrict__ in, bf16* __restrict__ oh,
                        bf16* __restrict__ ol, int inR, int inC, int ldo,
                        float alpha) {
    __shared__ float tl[32][33];
    int n0 = blockIdx.x * 32, k0 = blockIdx.y * 32;
    #pragma unroll
    for (int j = 0; j < 4; j++) {
        int k = k0 + threadIdx.y + j * 8, n = n0 + threadIdx.x;
        tl[threadIdx.y + j * 8][threadIdx.x] =
            (k < inR && n < inC) ? in[(size_t)k * inC + n] : 0.f;
    }
    __syncthreads();
    #pragma unroll
    for (int j = 0; j < 4; j++) {
        int n = n0 + threadIdx.y + j * 8, k = k0 + threadIdx.x;
        bf16 h, l;
        split2(alpha * tl[threadIdx.x][threadIdx.y + j * 8], h, l);
        oh[(size_t)n * ldo + k] = h;
        ol[(size_t)n * ldo + k] = l;
    }
}

// partD (6 k-slabs) + bias -> x4 planes [1024][512]
__global__ void k_x4() {
    int t = blockIdx.x * blockDim.x + threadIdx.x;
    if (t >= 1024 * 512) return;
    int row = t >> 9, col = t & 511;
    int b = row >> 3, g = row & 7;
    float v = 0.f;
    if (col < SO3) {
        int l = 6;
        while (col < c_off2[l]) l--;
        int d = 2 * l + 1, r = col - c_off2[l];
        int u = r / d, m = r - u * d, i = l * l + m;
        size_t o = (size_t)i * 128 * 104 + (size_t)b * 104 + g * d + u;
        float s = 0.f;
        #pragma unroll
        for (int zz = 0; zz < 6; zz++)
            s += d_partD[o + (size_t)zz * 49 * 128 * 104];
        v = s + d_bpsi[g * S2 + l * l + u] * d_q[l * l + m];
    }
    bf16 h, lo;
    split2(v, h, lo);
    d_x4h[t] = h;
    d_x4l[t] = lo;
}

__global__ void k_red6() {
    int t = blockIdx.x * blockDim.x + threadIdx.x;
    if (t >= 1024 * SO3) return;
    int row = t / SO3, col = t - row * SO3;
    float s = 0.f;
    #pragma unroll
    for (int zz = 0; zz < 8; zz++)
        s += d_part6[(size_t)zz * 1024 * 512 + (size_t)row * 512 + col];
    d_x5[t] = s;
}

__global__ void stageH_kernel(float* __restrict__ out) {
    int t = blockIdx.x * blockDim.x + threadIdx.x;
    if (t >= B_ * SO3) return;
    int b = t / SO3, j = t - b * SO3;
    int l = 6;
    while (j < c_off2[l]) l--;
    int d = 2 * l + 1;
    int r = j - c_off2[l];
    int v = r / d, m = r - v * d;
    float acc = 0.f;
    #pragma unroll
    for (int f = 0; f < G_; f++) {
        const float* xr = d_x5 + (size_t)(b * G_ + f) * SO3 + c_off2[l];
        const float* pr = d_psi2 + f * SO3 + c_off2[l];
        for (int u = 0; u < d; u++) acc += xr[u * d + m] * pr[u * d + v];
    }
    out[t] = acc * (1.0f / sqrtf(8.0f * d));
}

// ---------------------------------------------------------------------------
// Host launcher — multi-stream fork/join (capture-legal via events)
// ---------------------------------------------------------------------------
extern "C" void kernel_launch(void* const* d_in, const int* in_sizes, int n_in,
                              void* d_out, int out_size) {
    const float* fmap     = (const float*)d_in[0];
    const float* conv_w   = (const float*)d_in[1];
    const float* conv_b   = (const float*)d_in[2];
    const float* proj_w   = (const float*)d_in[3];
    const float* proj_Y   = (const float*)d_in[4];
    const float* fs_w     = (const float*)d_in[5];
    const float* fs_Y     = (const float*)d_in[6];
    const float* act_to   = (const float*)d_in[7];
    const float* act_from = (const float*)d_in[8];
    const float* so3_w    = (const float*)d_in[9];
    const float* so3_D    = (const float*)d_in[10];
    float* out = (float*)d_out;

    float *pPsi, *pPartD, *pPart6;
    bf16 *pADh, *pADl, *pW2th, *pW2tl, *pX4h, *pX4l, *pB5h, *pB5l;
    bf16 *pGh, *pGl, *pB6h, *pB6l, *pCwh, *pCwl, *pBWh, *pBWl;
    cudaGetSymbolAddress((void**)&pPsi,   d_psi);
    cudaGetSymbolAddress((void**)&pPartD, d_partD);
    cudaGetSymbolAddress((void**)&pPart6, d_part6);
    cudaGetSymbolAddress((void**)&pADh,   d_ADh);
    cudaGetSymbolAddress((void**)&pADl,   d_ADl);
    cudaGetSymbolAddress((void**)&pW2th,  d_W2th);
    cudaGetSymbolAddress((void**)&pW2tl,  d_W2tl);
    cudaGetSymbolAddress((void**)&pX4h,   d_x4h);
    cudaGetSymbolAddress((void**)&pX4l,   d_x4l);
    cudaGetSymbolAddress((void**)&pB5h,   d_bt5h);
    cudaGetSymbolAddress((void**)&pB5l,   d_bt5l);
    cudaGetSymbolAddress((void**)&pGh,    d_gacth);
    cudaGetSymbolAddress((void**)&pGl,    d_gactl);
    cudaGetSymbolAddress((void**)&pB6h,   d_bt6h);
    cudaGetSymbolAddress((void**)&pB6l,   d_bt6l);
    cudaGetSymbolAddress((void**)&pCwh,   d_cwTh);
    cudaGetSymbolAddress((void**)&pCwl,   d_cwTl);
    cudaGetSymbolAddress((void**)&pBWh,   d_btWh);
    cudaGetSymbolAddress((void**)&pBWl,   d_btWl);

    auto* kPsi = mmag_f<false, true, 64>;
    auto* kW2p = mmag_p<false, 2, false>;
    auto* kSD  = mmag_p<false, 0, true >;
    auto* kS5  = mmag_p<true,  1, false>;
    auto* kS6  = mmag_p<false, 0, false>;
    constexpr int SMP = 2 * 2 * 2 * 128 * 40 * 2;   // 81920 B
    cudaFuncSetAttribute(kW2p, cudaFuncAttributeMaxDynamicSharedMemorySize, SMP);
    cudaFuncSetAttribute(kSD,  cudaFuncAttributeMaxDynamicSharedMemorySize, SMP);
    cudaFuncSetAttribute(kS5,  cudaFuncAttributeMaxDynamicSharedMemorySize, SMP);
    cudaFuncSetAttribute(kS6,  cudaFuncAttributeMaxDynamicSharedMemorySize, SMP);

    // one-time host-side infra (no device memory, identical GPU work per call)
    static cudaStream_t s1 = nullptr, s2 = nullptr;
    static cudaEvent_t evRoot = nullptr, evW2 = nullptr, evBps = nullptr;
    static cudaEvent_t evAux = nullptr, evCw = nullptr;
    if (s1 == nullptr) {
        cudaStreamCreateWithFlags(&s1, cudaStreamNonBlocking);
        cudaStreamCreateWithFlags(&s2, cudaStreamNonBlocking);
        cudaEventCreateWithFlags(&evRoot, cudaEventDisableTiming);
        cudaEventCreateWithFlags(&evW2,   cudaEventDisableTiming);
        cudaEventCreateWithFlags(&evBps,  cudaEventDisableTiming);
        cudaEventCreateWithFlags(&evAux,  cudaEventDisableTiming);
        cudaEventCreateWithFlags(&evCw,   cudaEventDisableTiming);
    }

    // fork: s1 (W2 chain), s2 (operand preps) join the capture via evRoot
    cudaEventRecord(evRoot, 0);
    cudaStreamWaitEvent(s1, evRoot, 0);
    cudaStreamWaitEvent(s2, evRoot, 0);

    // main chain
    k_Pq<<<1, 256>>>(proj_w, proj_Y);
    kAD_kernel<<<2048, 256>>>(fmap, pADh, pADl);

    // s2: conv_w^T planes first (kW2p needs them), then the act preps
    k_tpose<<<dim3(64, 16), dim3(32, 8), 0, s2>>>(conv_w, pCwh, pCwl,
                                                  FIN, C_, 512, RS512);
    cudaEventRecord(evCw, s2);
    k_psi2<<<(G_ * SO3 * 32 + 127) / 128, 128, 0, s2>>>(so3_w, so3_D);
    k_tpose<<<dim3(128, 15), dim3(32, 8), 0, s2>>>(act_to,   pB5h, pB5l,
                                                   SO3, NG, 480, 1.f);
    k_tpose<<<dim3(16, 128), dim3(32, 8), 0, s2>>>(act_from, pB6h, pB6l,
                                                   NG, SO3, 4096, 1.f);
    cudaEventRecord(evAux, s2);

    // s1: psi (plain) -> btW planes -> W2 (pipelined) -> bpsi
    kPsi<<<dim3(1, 32, 1), 256, 0, s1>>>(fs_w, fs_Y, pPsi,
                                         NP, S2, S2, NP, S2, RS192, 6);
    k_tposePsi<<<dim3(8, 8), 256, 0, s1>>>();
    cudaStreamWaitEvent(s1, evCw, 0);
    // W2 (pipelined): M=2048, N=392(512 pad), K=512 -> permuted W2t store
    kW2p<<<dim3(4, 16, 1), 256, SMP, s1>>>(pCwh, pCwl, pBWh, pBWl,
        (float*)0, (bf16*)0, (bf16*)0,
        512, 512, 0, GI, 4, 16, 512, 1, 512, 0, 0, 0, 0);
    cudaEventRecord(evW2, s1);
    k_bpsi<<<(GI + 31) / 32, 256, 0, s1>>>(conv_b);
    cudaEventRecord(evBps, s1);

    cudaStreamWaitEvent(0, evW2, 0);
    // stageD: 49 batches (M=128, N=8d, K=2048), split-K x6 -> 294 CTAs (1 wave)
    kSD<<<dim3(1, 1, 294), 256, SMP>>>(pADh, pADl, pW2th, pW2tl,
        pPartD, (bf16*)0, (bf16*)0,
        C_, C_, 104, 104, 4, 11, 352, 6, C_,
        BC, (size_t)128 * C_, (size_t)128 * 104, (size_t)49 * 128 * 104);

    cudaStreamWaitEvent(0, evBps, 0);
    k_x4<<<(1024 * 512 + 255) / 256, 256>>>();

    cudaStreamWaitEvent(0, evAux, 0);
    // stage5: gact planes = relu(x4 @ act_to)  (M=1024, N=4096, K=480)
    kS5<<<dim3(32, 8, 1), 256, SMP>>>(pX4h, pX4l, pB5h, pB5l,
        (float*)0, pGh, pGl,
        512, 480, 4096, 4096, 4, 15, 480, 1, 480, 0, 0, 0, 0);

    // stage6: part6[z] = gact @ act_from  (M=1024, N=512, K=4096), split-K x8
    kS6<<<dim3(4, 8, 8), 256, SMP>>>(pGh, pGl, pB6h, pB6l,
        pPart6, (bf16*)0, (bf16*)0,
        4096, 4096, 512, 512, 4, 16, 512, 8, 4096,
        0, 0, 0, (size_t)1024 * 512);
    k_red6<<<(1024 * SO3 + 255) / 256, 256>>>();

    stageH_kernel<<<(B_ * SO3 + 255) / 256, 256>>>(out);
}